// round 1
// baseline (speedup 1.0000x reference)
#include <cuda_runtime.h>

#define BATCH 4
#define SEQ   2048
#define DIM   1024
#define NORM_FACT 0.03125f   // 1/sqrt(1024), applied POST-softmax per reference

// Scratch (allocation-free rule: __device__ globals)
__device__ __align__(256) float g_Q[(size_t)BATCH * SEQ * DIM];
__device__ __align__(256) float g_K[(size_t)BATCH * SEQ * DIM];
__device__ __align__(256) float g_V[(size_t)BATCH * SEQ * DIM];
__device__ __align__(256) float g_P[(size_t)BATCH * SEQ * SEQ];

// ---------------------------------------------------------------------------
// NT GEMM: C[M,N] = A[M,K] * B[N,K]^T (+ bias[n]), all row-major.
// 128x128 block, K-tile 8, 256 threads, 8x8 per-thread microtile.
// ---------------------------------------------------------------------------
__global__ __launch_bounds__(256, 2)
void gemm_nt(const float* __restrict__ A, const float* __restrict__ B,
             const float* __restrict__ bias, float* __restrict__ C,
             int M, int N, int K, size_t sA, size_t sB, size_t sC)
{
    A += blockIdx.z * sA;
    B += blockIdx.z * sB;
    C += blockIdx.z * sC;

    __shared__ float As[8][128];
    __shared__ float Bs[8][128];

    const int tid = threadIdx.x;
    const int tx = tid & 15;        // 0..15 -> N
    const int ty = tid >> 4;        // 0..15 -> M
    const int bm = blockIdx.y * 128;
    const int bn = blockIdx.x * 128;

    const int lrow = tid >> 1;          // 0..127
    const int lcol = (tid & 1) * 4;     // 0 or 4
    const float* Ap = A + (size_t)(bm + lrow) * K + lcol;
    const float* Bp = B + (size_t)(bn + lrow) * K + lcol;

    float acc[8][8] = {};

    for (int k0 = 0; k0 < K; k0 += 8) {
        float4 va = *(const float4*)(Ap + k0);
        float4 vb = *(const float4*)(Bp + k0);
        As[lcol + 0][lrow] = va.x; As[lcol + 1][lrow] = va.y;
        As[lcol + 2][lrow] = va.z; As[lcol + 3][lrow] = va.w;
        Bs[lcol + 0][lrow] = vb.x; Bs[lcol + 1][lrow] = vb.y;
        Bs[lcol + 2][lrow] = vb.z; Bs[lcol + 3][lrow] = vb.w;
        __syncthreads();

        #pragma unroll
        for (int kk = 0; kk < 8; kk++) {
            float4 a0 = *(const float4*)&As[kk][ty * 8];
            float4 a1 = *(const float4*)&As[kk][ty * 8 + 4];
            float4 b0 = *(const float4*)&Bs[kk][tx * 8];
            float4 b1 = *(const float4*)&Bs[kk][tx * 8 + 4];
            float a[8] = {a0.x, a0.y, a0.z, a0.w, a1.x, a1.y, a1.z, a1.w};
            float b[8] = {b0.x, b0.y, b0.z, b0.w, b1.x, b1.y, b1.z, b1.w};
            #pragma unroll
            for (int i = 0; i < 8; i++)
                #pragma unroll
                for (int j = 0; j < 8; j++)
                    acc[i][j] = fmaf(a[i], b[j], acc[i][j]);
        }
        __syncthreads();
    }

    #pragma unroll
    for (int i = 0; i < 8; i++) {
        const int m = bm + ty * 8 + i;
        #pragma unroll
        for (int j = 0; j < 8; j += 4) {
            const int n = bn + tx * 8 + j;
            float4 v;
            v.x = acc[i][j + 0]; v.y = acc[i][j + 1];
            v.z = acc[i][j + 2]; v.w = acc[i][j + 3];
            if (bias) {
                v.x += bias[n + 0]; v.y += bias[n + 1];
                v.z += bias[n + 2]; v.w += bias[n + 3];
            }
            *(float4*)(C + (size_t)m * N + n) = v;
        }
    }
}

// ---------------------------------------------------------------------------
// NN GEMM: C[M,N] = A[M,K] * B[K,N], all row-major.
// ---------------------------------------------------------------------------
__global__ __launch_bounds__(256, 2)
void gemm_nn(const float* __restrict__ A, const float* __restrict__ B,
             float* __restrict__ C,
             int M, int N, int K, size_t sA, size_t sB, size_t sC)
{
    A += blockIdx.z * sA;
    B += blockIdx.z * sB;
    C += blockIdx.z * sC;

    __shared__ float As[8][128];
    __shared__ float Bs[8][128];

    const int tid = threadIdx.x;
    const int tx = tid & 15;
    const int ty = tid >> 4;
    const int bm = blockIdx.y * 128;
    const int bn = blockIdx.x * 128;

    const int larow = tid >> 1;
    const int lacol = (tid & 1) * 4;
    const int lbrow = tid >> 5;          // 0..7
    const int lbcol = (tid & 31) * 4;    // 0..124
    const float* Ap = A + (size_t)(bm + larow) * K + lacol;
    const float* Bp = B + (size_t)lbrow * N + bn + lbcol;

    float acc[8][8] = {};

    for (int k0 = 0; k0 < K; k0 += 8) {
        float4 va = *(const float4*)(Ap + k0);
        float4 vb = *(const float4*)(Bp + (size_t)k0 * N);
        As[lacol + 0][larow] = va.x; As[lacol + 1][larow] = va.y;
        As[lacol + 2][larow] = va.z; As[lacol + 3][larow] = va.w;
        *(float4*)&Bs[lbrow][lbcol] = vb;
        __syncthreads();

        #pragma unroll
        for (int kk = 0; kk < 8; kk++) {
            float4 a0 = *(const float4*)&As[kk][ty * 8];
            float4 a1 = *(const float4*)&As[kk][ty * 8 + 4];
            float4 b0 = *(const float4*)&Bs[kk][tx * 8];
            float4 b1 = *(const float4*)&Bs[kk][tx * 8 + 4];
            float a[8] = {a0.x, a0.y, a0.z, a0.w, a1.x, a1.y, a1.z, a1.w};
            float b[8] = {b0.x, b0.y, b0.z, b0.w, b1.x, b1.y, b1.z, b1.w};
            #pragma unroll
            for (int i = 0; i < 8; i++)
                #pragma unroll
                for (int j = 0; j < 8; j++)
                    acc[i][j] = fmaf(a[i], b[j], acc[i][j]);
        }
        __syncthreads();
    }

    #pragma unroll
    for (int i = 0; i < 8; i++) {
        const int m = bm + ty * 8 + i;
        #pragma unroll
        for (int j = 0; j < 8; j += 4) {
            const int n = bn + tx * 8 + j;
            float4 v;
            v.x = acc[i][j + 0]; v.y = acc[i][j + 1];
            v.z = acc[i][j + 2]; v.w = acc[i][j + 3];
            *(float4*)(C + (size_t)m * N + n) = v;
        }
    }
}

// ---------------------------------------------------------------------------
// Row softmax over SEQ=2048 elements, fused with * NORM_FACT. In-place on g_P.
// One block (256 threads) per row; 8 elems/thread.
// ---------------------------------------------------------------------------
__global__ __launch_bounds__(256)
void softmax_rows(float* __restrict__ S)
{
    float* row = S + (size_t)blockIdx.x * SEQ;
    const int tid = threadIdx.x;

    float4 v0 = *(const float4*)(row + tid * 4);
    float4 v1 = *(const float4*)(row + 1024 + tid * 4);

    float m = fmaxf(fmaxf(fmaxf(v0.x, v0.y), fmaxf(v0.z, v0.w)),
                    fmaxf(fmaxf(v1.x, v1.y), fmaxf(v1.z, v1.w)));
    #pragma unroll
    for (int o = 16; o > 0; o >>= 1)
        m = fmaxf(m, __shfl_xor_sync(0xffffffffu, m, o));

    __shared__ float red[8];
    const int wid = tid >> 5, lane = tid & 31;
    if (lane == 0) red[wid] = m;
    __syncthreads();
    m = red[0];
    #pragma unroll
    for (int w = 1; w < 8; w++) m = fmaxf(m, red[w]);

    v0.x = __expf(v0.x - m); v0.y = __expf(v0.y - m);
    v0.z = __expf(v0.z - m); v0.w = __expf(v0.w - m);
    v1.x = __expf(v1.x - m); v1.y = __expf(v1.y - m);
    v1.z = __expf(v1.z - m); v1.w = __expf(v1.w - m);

    float s = (v0.x + v0.y) + (v0.z + v0.w) + (v1.x + v1.y) + (v1.z + v1.w);
    #pragma unroll
    for (int o = 16; o > 0; o >>= 1)
        s += __shfl_xor_sync(0xffffffffu, s, o);

    __syncthreads();   // red[] reuse
    __shared__ float red2[8];
    if (lane == 0) red2[wid] = s;
    __syncthreads();
    s = red2[0];
    #pragma unroll
    for (int w = 1; w < 8; w++) s += red2[w];

    const float scale = NORM_FACT / s;
    v0.x *= scale; v0.y *= scale; v0.z *= scale; v0.w *= scale;
    v1.x *= scale; v1.y *= scale; v1.z *= scale; v1.w *= scale;

    *(float4*)(row + tid * 4)        = v0;
    *(float4*)(row + 1024 + tid * 4) = v1;
}

// ---------------------------------------------------------------------------
extern "C" void kernel_launch(void* const* d_in, const int* in_sizes, int n_in,
                              void* d_out, int out_size)
{
    const float* x  = (const float*)d_in[0];
    const float* Wq = (const float*)d_in[1];
    const float* bq = (const float*)d_in[2];
    const float* Wk = (const float*)d_in[3];
    const float* bk = (const float*)d_in[4];
    const float* Wv = (const float*)d_in[5];
    const float* bv = (const float*)d_in[6];
    float* out = (float*)d_out;

    float *Q, *K, *V, *P;
    cudaGetSymbolAddress((void**)&Q, g_Q);
    cudaGetSymbolAddress((void**)&K, g_K);
    cudaGetSymbolAddress((void**)&V, g_V);
    cudaGetSymbolAddress((void**)&P, g_P);

    // QKV projections: [8192,1024] = x[8192,1024] @ W^T + b
    {
        dim3 grid(DIM / 128, (BATCH * SEQ) / 128, 1);
        gemm_nt<<<grid, 256>>>(x, Wq, bq, Q, BATCH * SEQ, DIM, DIM, 0, 0, 0);
        gemm_nt<<<grid, 256>>>(x, Wk, bk, K, BATCH * SEQ, DIM, DIM, 0, 0, 0);
        gemm_nt<<<grid, 256>>>(x, Wv, bv, V, BATCH * SEQ, DIM, DIM, 0, 0, 0);
    }

    // scores[b] = Q[b] @ K[b]^T   (batched via gridDim.z)
    {
        dim3 grid(SEQ / 128, SEQ / 128, BATCH);
        gemm_nt<<<grid, 256>>>(Q, K, nullptr, P, SEQ, SEQ, DIM,
                               (size_t)SEQ * DIM, (size_t)SEQ * DIM,
                               (size_t)SEQ * SEQ);
    }

    // softmax rows (with 1/sqrt(Dk) folded in)
    softmax_rows<<<BATCH * SEQ, 256>>>(P);

    // out[b] = P[b] @ V[b]
    {
        dim3 grid(DIM / 128, SEQ / 128, BATCH);
        gemm_nn<<<grid, 256>>>(P, V, out, SEQ, DIM, SEQ,
                               (size_t)SEQ * SEQ, (size_t)SEQ * DIM,
                               (size_t)SEQ * DIM);
    }
}

// round 2
// speedup vs baseline: 1.0110x; 1.0110x over previous
#include <cuda_runtime.h>

#define BATCH 4
#define SEQ   2048
#define DIM   1024
#define NORM_FACT 0.03125f   // 1/sqrt(1024), applied POST-softmax per reference

// Scratch (allocation-free rule: __device__ globals)
__device__ __align__(256) float g_Q[(size_t)BATCH * SEQ * DIM];
__device__ __align__(256) float g_K[(size_t)BATCH * SEQ * DIM];
__device__ __align__(256) float g_V[(size_t)BATCH * SEQ * DIM];
__device__ __align__(256) float g_P[(size_t)BATCH * SEQ * SEQ];

#define BK   16
#define LDA  132   // padded row stride (132*4=528B, 16B-aligned)

// ---------------------------------------------------------------------------
// NT GEMM: C[M,N] = A[M,K] * B[N,K]^T (+ bias[n]), all row-major.
// 128x128 block, K-tile 16 double-buffered, 256 threads, 8x8 microtile.
// ---------------------------------------------------------------------------
__global__ __launch_bounds__(256, 2)
void gemm_nt(const float* __restrict__ A, const float* __restrict__ B,
             const float* __restrict__ bias, float* __restrict__ C,
             int M, int N, int K, size_t sA, size_t sB, size_t sC)
{
    A += blockIdx.z * sA;
    B += blockIdx.z * sB;
    C += blockIdx.z * sC;

    __shared__ float As[2][BK][LDA];
    __shared__ float Bs[2][BK][LDA];

    const int tid = threadIdx.x;
    const int tx = tid & 15;        // 0..15 -> N
    const int ty = tid >> 4;        // 0..15 -> M
    const int bm = blockIdx.y * 128;
    const int bn = blockIdx.x * 128;

    // loader: thread covers row (tid>>1), k-range (tid&1)*8 .. +7
    const int lrow = tid >> 1;
    const int lk   = (tid & 1) * 8;
    const float* Ap = A + (size_t)(bm + lrow) * K + lk;
    const float* Bp = B + (size_t)(bn + lrow) * K + lk;

    float acc[8][8] = {};

    // preload tile 0
    {
        float4 a0 = *(const float4*)(Ap);
        float4 a1 = *(const float4*)(Ap + 4);
        float4 b0 = *(const float4*)(Bp);
        float4 b1 = *(const float4*)(Bp + 4);
        As[0][lk + 0][lrow] = a0.x; As[0][lk + 1][lrow] = a0.y;
        As[0][lk + 2][lrow] = a0.z; As[0][lk + 3][lrow] = a0.w;
        As[0][lk + 4][lrow] = a1.x; As[0][lk + 5][lrow] = a1.y;
        As[0][lk + 6][lrow] = a1.z; As[0][lk + 7][lrow] = a1.w;
        Bs[0][lk + 0][lrow] = b0.x; Bs[0][lk + 1][lrow] = b0.y;
        Bs[0][lk + 2][lrow] = b0.z; Bs[0][lk + 3][lrow] = b0.w;
        Bs[0][lk + 4][lrow] = b1.x; Bs[0][lk + 5][lrow] = b1.y;
        Bs[0][lk + 6][lrow] = b1.z; Bs[0][lk + 7][lrow] = b1.w;
    }
    __syncthreads();

    int buf = 0;
    for (int k0 = 0; k0 < K; k0 += BK) {
        const bool has_next = (k0 + BK) < K;
        float4 na0, na1, nb0, nb1;
        if (has_next) {
            na0 = *(const float4*)(Ap + k0 + BK);
            na1 = *(const float4*)(Ap + k0 + BK + 4);
            nb0 = *(const float4*)(Bp + k0 + BK);
            nb1 = *(const float4*)(Bp + k0 + BK + 4);
        }

        #pragma unroll
        for (int kk = 0; kk < BK; kk++) {
            float4 a0 = *(const float4*)&As[buf][kk][ty * 8];
            float4 a1 = *(const float4*)&As[buf][kk][ty * 8 + 4];
            float4 b0 = *(const float4*)&Bs[buf][kk][tx * 8];
            float4 b1 = *(const float4*)&Bs[buf][kk][tx * 8 + 4];
            float a[8] = {a0.x, a0.y, a0.z, a0.w, a1.x, a1.y, a1.z, a1.w};
            float b[8] = {b0.x, b0.y, b0.z, b0.w, b1.x, b1.y, b1.z, b1.w};
            #pragma unroll
            for (int i = 0; i < 8; i++)
                #pragma unroll
                for (int j = 0; j < 8; j++)
                    acc[i][j] = fmaf(a[i], b[j], acc[i][j]);
        }

        if (has_next) {
            const int nb = buf ^ 1;
            As[nb][lk + 0][lrow] = na0.x; As[nb][lk + 1][lrow] = na0.y;
            As[nb][lk + 2][lrow] = na0.z; As[nb][lk + 3][lrow] = na0.w;
            As[nb][lk + 4][lrow] = na1.x; As[nb][lk + 5][lrow] = na1.y;
            As[nb][lk + 6][lrow] = na1.z; As[nb][lk + 7][lrow] = na1.w;
            Bs[nb][lk + 0][lrow] = nb0.x; Bs[nb][lk + 1][lrow] = nb0.y;
            Bs[nb][lk + 2][lrow] = nb0.z; Bs[nb][lk + 3][lrow] = nb0.w;
            Bs[nb][lk + 4][lrow] = nb1.x; Bs[nb][lk + 5][lrow] = nb1.y;
            Bs[nb][lk + 6][lrow] = nb1.z; Bs[nb][lk + 7][lrow] = nb1.w;
            __syncthreads();
            buf = nb;
        }
    }

    #pragma unroll
    for (int i = 0; i < 8; i++) {
        const int m = bm + ty * 8 + i;
        #pragma unroll
        for (int j = 0; j < 8; j += 4) {
            const int n = bn + tx * 8 + j;
            float4 v;
            v.x = acc[i][j + 0]; v.y = acc[i][j + 1];
            v.z = acc[i][j + 2]; v.w = acc[i][j + 3];
            if (bias) {
                v.x += bias[n + 0]; v.y += bias[n + 1];
                v.z += bias[n + 2]; v.w += bias[n + 3];
            }
            *(float4*)(C + (size_t)m * N + n) = v;
        }
    }
}

// ---------------------------------------------------------------------------
// NN GEMM: C[M,N] = A[M,K] * B[K,N], all row-major. Same blocking.
// ---------------------------------------------------------------------------
__global__ __launch_bounds__(256, 2)
void gemm_nn(const float* __restrict__ A, const float* __restrict__ B,
             float* __restrict__ C,
             int M, int N, int K, size_t sA, size_t sB, size_t sC)
{
    A += blockIdx.z * sA;
    B += blockIdx.z * sB;
    C += blockIdx.z * sC;

    __shared__ float As[2][BK][LDA];
    __shared__ float Bs[2][BK][LDA];

    const int tid = threadIdx.x;
    const int tx = tid & 15;
    const int ty = tid >> 4;
    const int bm = blockIdx.y * 128;
    const int bn = blockIdx.x * 128;

    // A loader (transposed store): row tid>>1, k-range (tid&1)*8
    const int larow = tid >> 1;
    const int lak   = (tid & 1) * 8;
    const float* Ap = A + (size_t)(bm + larow) * K + lak;

    // B loader (natural store): 16 rows x 32 float4; 2 float4 per thread
    const int lbk0 = tid >> 5;            // 0..7   (first half rows)
    const int lbc  = (tid & 31) * 4;      // 0..124
    const float* Bp = B + bn + lbc;

    float acc[8][8] = {};

    // preload tile 0
    {
        float4 a0 = *(const float4*)(Ap);
        float4 a1 = *(const float4*)(Ap + 4);
        As[0][lak + 0][larow] = a0.x; As[0][lak + 1][larow] = a0.y;
        As[0][lak + 2][larow] = a0.z; As[0][lak + 3][larow] = a0.w;
        As[0][lak + 4][larow] = a1.x; As[0][lak + 5][larow] = a1.y;
        As[0][lak + 6][larow] = a1.z; As[0][lak + 7][larow] = a1.w;
        float4 b0 = *(const float4*)(Bp + (size_t)lbk0 * N);
        float4 b1 = *(const float4*)(Bp + (size_t)(lbk0 + 8) * N);
        *(float4*)&Bs[0][lbk0][lbc]     = b0;
        *(float4*)&Bs[0][lbk0 + 8][lbc] = b1;
    }
    __syncthreads();

    int buf = 0;
    for (int k0 = 0; k0 < K; k0 += BK) {
        const bool has_next = (k0 + BK) < K;
        float4 na0, na1, nb0, nb1;
        if (has_next) {
            na0 = *(const float4*)(Ap + k0 + BK);
            na1 = *(const float4*)(Ap + k0 + BK + 4);
            nb0 = *(const float4*)(Bp + (size_t)(k0 + BK + lbk0) * N);
            nb1 = *(const float4*)(Bp + (size_t)(k0 + BK + lbk0 + 8) * N);
        }

        #pragma unroll
        for (int kk = 0; kk < BK; kk++) {
            float4 a0 = *(const float4*)&As[buf][kk][ty * 8];
            float4 a1 = *(const float4*)&As[buf][kk][ty * 8 + 4];
            float4 b0 = *(const float4*)&Bs[buf][kk][tx * 8];
            float4 b1 = *(const float4*)&Bs[buf][kk][tx * 8 + 4];
            float a[8] = {a0.x, a0.y, a0.z, a0.w, a1.x, a1.y, a1.z, a1.w};
            float b[8] = {b0.x, b0.y, b0.z, b0.w, b1.x, b1.y, b1.z, b1.w};
            #pragma unroll
            for (int i = 0; i < 8; i++)
                #pragma unroll
                for (int j = 0; j < 8; j++)
                    acc[i][j] = fmaf(a[i], b[j], acc[i][j]);
        }

        if (has_next) {
            const int nb = buf ^ 1;
            As[nb][lak + 0][larow] = na0.x; As[nb][lak + 1][larow] = na0.y;
            As[nb][lak + 2][larow] = na0.z; As[nb][lak + 3][larow] = na0.w;
            As[nb][lak + 4][larow] = na1.x; As[nb][lak + 5][larow] = na1.y;
            As[nb][lak + 6][larow] = na1.z; As[nb][lak + 7][larow] = na1.w;
            *(float4*)&Bs[nb][lbk0][lbc]     = nb0;
            *(float4*)&Bs[nb][lbk0 + 8][lbc] = nb1;
            __syncthreads();
            buf = nb;
        }
    }

    #pragma unroll
    for (int i = 0; i < 8; i++) {
        const int m = bm + ty * 8 + i;
        #pragma unroll
        for (int j = 0; j < 8; j += 4) {
            const int n = bn + tx * 8 + j;
            float4 v;
            v.x = acc[i][j + 0]; v.y = acc[i][j + 1];
            v.z = acc[i][j + 2]; v.w = acc[i][j + 3];
            *(float4*)(C + (size_t)m * N + n) = v;
        }
    }
}

// ---------------------------------------------------------------------------
// Row softmax over SEQ=2048 elements, fused with * NORM_FACT. In-place on g_P.
// ---------------------------------------------------------------------------
__global__ __launch_bounds__(256)
void softmax_rows(float* __restrict__ S)
{
    float* row = S + (size_t)blockIdx.x * SEQ;
    const int tid = threadIdx.x;

    float4 v0 = *(const float4*)(row + tid * 4);
    float4 v1 = *(const float4*)(row + 1024 + tid * 4);

    float m = fmaxf(fmaxf(fmaxf(v0.x, v0.y), fmaxf(v0.z, v0.w)),
                    fmaxf(fmaxf(v1.x, v1.y), fmaxf(v1.z, v1.w)));
    #pragma unroll
    for (int o = 16; o > 0; o >>= 1)
        m = fmaxf(m, __shfl_xor_sync(0xffffffffu, m, o));

    __shared__ float red[8];
    const int wid = tid >> 5, lane = tid & 31;
    if (lane == 0) red[wid] = m;
    __syncthreads();
    m = red[0];
    #pragma unroll
    for (int w = 1; w < 8; w++) m = fmaxf(m, red[w]);

    v0.x = __expf(v0.x - m); v0.y = __expf(v0.y - m);
    v0.z = __expf(v0.z - m); v0.w = __expf(v0.w - m);
    v1.x = __expf(v1.x - m); v1.y = __expf(v1.y - m);
    v1.z = __expf(v1.z - m); v1.w = __expf(v1.w - m);

    float s = (v0.x + v0.y) + (v0.z + v0.w) + (v1.x + v1.y) + (v1.z + v1.w);
    #pragma unroll
    for (int o = 16; o > 0; o >>= 1)
        s += __shfl_xor_sync(0xffffffffu, s, o);

    __syncthreads();
    __shared__ float red2[8];
    if (lane == 0) red2[wid] = s;
    __syncthreads();
    s = red2[0];
    #pragma unroll
    for (int w = 1; w < 8; w++) s += red2[w];

    const float scale = NORM_FACT / s;
    v0.x *= scale; v0.y *= scale; v0.z *= scale; v0.w *= scale;
    v1.x *= scale; v1.y *= scale; v1.z *= scale; v1.w *= scale;

    *(float4*)(row + tid * 4)        = v0;
    *(float4*)(row + 1024 + tid * 4) = v1;
}

// ---------------------------------------------------------------------------
extern "C" void kernel_launch(void* const* d_in, const int* in_sizes, int n_in,
                              void* d_out, int out_size)
{
    const float* x  = (const float*)d_in[0];
    const float* Wq = (const float*)d_in[1];
    const float* bq = (const float*)d_in[2];
    const float* Wk = (const float*)d_in[3];
    const float* bk = (const float*)d_in[4];
    const float* Wv = (const float*)d_in[5];
    const float* bv = (const float*)d_in[6];
    float* out = (float*)d_out;

    float *Q, *K, *V, *P;
    cudaGetSymbolAddress((void**)&Q, g_Q);
    cudaGetSymbolAddress((void**)&K, g_K);
    cudaGetSymbolAddress((void**)&V, g_V);
    cudaGetSymbolAddress((void**)&P, g_P);

    // QKV projections: [8192,1024] = x[8192,1024] @ W^T + b
    {
        dim3 grid(DIM / 128, (BATCH * SEQ) / 128, 1);
        gemm_nt<<<grid, 256>>>(x, Wq, bq, Q, BATCH * SEQ, DIM, DIM, 0, 0, 0);
        gemm_nt<<<grid, 256>>>(x, Wk, bk, K, BATCH * SEQ, DIM, DIM, 0, 0, 0);
        gemm_nt<<<grid, 256>>>(x, Wv, bv, V, BATCH * SEQ, DIM, DIM, 0, 0, 0);
    }

    // scores[b] = Q[b] @ K[b]^T   (batched via gridDim.z)
    {
        dim3 grid(SEQ / 128, SEQ / 128, BATCH);
        gemm_nt<<<grid, 256>>>(Q, K, nullptr, P, SEQ, SEQ, DIM,
                               (size_t)SEQ * DIM, (size_t)SEQ * DIM,
                               (size_t)SEQ * SEQ);
    }

    // softmax rows (with 1/sqrt(Dk) folded in)
    softmax_rows<<<BATCH * SEQ, 256>>>(P);

    // out[b] = P[b] @ V[b]
    {
        dim3 grid(DIM / 128, SEQ / 128, BATCH);
        gemm_nn<<<grid, 256>>>(P, V, out, SEQ, DIM, SEQ,
                               (size_t)SEQ * SEQ, (size_t)SEQ * DIM,
                               (size_t)SEQ * DIM);
    }
}

// round 4
// speedup vs baseline: 1.2537x; 1.2401x over previous
#include <cuda_runtime.h>
#include <cuda_bf16.h>
#include <cstdint>

#define BATCH 4
#define SEQ   2048
#define DIM   1024
#define NORM_FACT 0.03125f   // 1/sqrt(1024), applied POST-softmax per reference

// Scratch (allocation-free rule: __device__ globals)
__device__ __align__(256) float g_Q [(size_t)BATCH * SEQ * DIM];
__device__ __align__(256) float g_K [(size_t)BATCH * SEQ * DIM];
__device__ __align__(256) float g_V [(size_t)BATCH * SEQ * DIM];
__device__ __align__(256) float g_Vt[(size_t)BATCH * SEQ * DIM];
__device__ __align__(256) float g_P [(size_t)BATCH * SEQ * SEQ];

// ---------------------------------------------------------------------------
// Smem layout per stage: Ah(10240) Al(10240) Bh(10240) Bl(10240) = 40960 B.
// Tiles are 128 rows x 32 bf16, row stride 80 B (40 halves) -> ldmatrix
// conflict-free (row banks {0,20,8,28,16,4,24,12} all distinct).
// ---------------------------------------------------------------------------
#define ROWB   80
#define TILEB  (128 * ROWB)          // 10240
#define STAGE  (4 * TILEB)           // 40960
#define SMEM_TOTAL (2 * STAGE)       // 81920

extern __shared__ char dsm[];

__device__ __forceinline__ uint32_t smem_u32(const void* p) {
    uint32_t a;
    asm("{ .reg .u64 t; cvta.to.shared.u64 t, %1; cvt.u32.u64 %0, t; }"
        : "=r"(a) : "l"(p));
    return a;
}

#define LDSM4(R, addr)                                                        \
    asm volatile("ldmatrix.sync.aligned.m8n8.x4.shared.b16 {%0,%1,%2,%3}, [%4];" \
                 : "=r"((R)[0]), "=r"((R)[1]), "=r"((R)[2]), "=r"((R)[3])     \
                 : "r"(addr))

#define MMA(cc, A, b0, b1)                                                    \
    asm volatile("mma.sync.aligned.m16n8k16.row.col.f32.bf16.bf16.f32 "       \
                 "{%0,%1,%2,%3},{%4,%5,%6,%7},{%8,%9},{%0,%1,%2,%3};"         \
                 : "+f"((cc)[0]), "+f"((cc)[1]), "+f"((cc)[2]), "+f"((cc)[3]) \
                 : "r"((A)[0]), "r"((A)[1]), "r"((A)[2]), "r"((A)[3]),        \
                   "r"(b0), "r"(b1))

__device__ __forceinline__ uint32_t pk(__nv_bfloat16 a, __nv_bfloat16 b) {
    return (uint32_t)__bfloat16_as_ushort(a) | ((uint32_t)__bfloat16_as_ushort(b) << 16);
}

__device__ __forceinline__ void split4(float4 v, uint2& h, uint2& l) {
    __nv_bfloat16 h0 = __float2bfloat16_rn(v.x);
    __nv_bfloat16 h1 = __float2bfloat16_rn(v.y);
    __nv_bfloat16 h2 = __float2bfloat16_rn(v.z);
    __nv_bfloat16 h3 = __float2bfloat16_rn(v.w);
    __nv_bfloat16 l0 = __float2bfloat16_rn(v.x - __bfloat162float(h0));
    __nv_bfloat16 l1 = __float2bfloat16_rn(v.y - __bfloat162float(h1));
    __nv_bfloat16 l2 = __float2bfloat16_rn(v.z - __bfloat162float(h2));
    __nv_bfloat16 l3 = __float2bfloat16_rn(v.w - __bfloat162float(h3));
    h.x = pk(h0, h1); h.y = pk(h2, h3);
    l.x = pk(l0, l1); l.y = pk(l2, l3);
}

// ---------------------------------------------------------------------------
// Split-precision NT GEMM on HMMA (mma.sync m16n8k16 bf16, fp32 accum):
//   C[M,N] = A[M,K](f32) * B[N,K]^T(f32) (+ bias[n])
// CTA tile 128x128, k-chunk 32 double-buffered, 8 warps (2x4), warp 64x32.
// ---------------------------------------------------------------------------
__global__ __launch_bounds__(256, 1)
void gemm_mma(const float* __restrict__ A, const float* __restrict__ B,
              const float* __restrict__ bias, float* __restrict__ C,
              int M, int N, int K, size_t sA, size_t sB, size_t sC)
{
    A += (size_t)blockIdx.z * sA;
    B += (size_t)blockIdx.z * sB;
    C += (size_t)blockIdx.z * sC;

    const int tid  = threadIdx.x;
    const int wid  = tid >> 5;
    const int lane = tid & 31;
    const int wm   = wid >> 2;        // 0..1
    const int wn   = wid & 3;         // 0..3
    const int bm = blockIdx.y * 128;
    const int bn = blockIdx.x * 128;

    // loader mapping: 4 float4 per matrix per thread
    const int lrow = tid >> 3;              // 0..31 (base row, +32*i)
    const int lf4  = tid & 7;               // float4 index in row
    const float* ApB = A + (size_t)(bm + lrow) * K + lf4 * 4;
    const float* BpB = B + (size_t)(bn + lrow) * K + lf4 * 4;
    const uint32_t stoff = (uint32_t)lrow * ROWB + (uint32_t)lf4 * 8;

    const uint32_t sb = smem_u32(dsm);
    // ldmatrix lane offset (same formula for A and B tiles)
    const uint32_t laneOff = (uint32_t)(lane & 15) * ROWB + (uint32_t)(lane >> 4) * 16;

    float acc[4][4][4] = {};

    // ---- initial fill: chunk 0 -> stage 0
    {
        char* st = dsm;
        #pragma unroll
        for (int i = 0; i < 4; i++) {
            float4 va = *(const float4*)(ApB + (size_t)(i * 32) * K);
            float4 vb = *(const float4*)(BpB + (size_t)(i * 32) * K);
            uint2 h, l;
            const uint32_t o = stoff + i * 32 * ROWB;
            split4(va, h, l);
            *(uint2*)(st + 0 * TILEB + o) = h;
            *(uint2*)(st + 1 * TILEB + o) = l;
            split4(vb, h, l);
            *(uint2*)(st + 2 * TILEB + o) = h;
            *(uint2*)(st + 3 * TILEB + o) = l;
        }
    }
    __syncthreads();

    const int NC = K >> 5;
    for (int c = 0; c < NC; c++) {
        const bool has_next = (c + 1) < NC;
        float4 pa[4], pb[4];
        if (has_next) {
            const int k1 = (c + 1) << 5;
            #pragma unroll
            for (int i = 0; i < 4; i++) {
                pa[i] = *(const float4*)(ApB + (size_t)(i * 32) * K + k1);
                pb[i] = *(const float4*)(BpB + (size_t)(i * 32) * K + k1);
            }
        }

        const uint32_t sbase = sb + (uint32_t)(c & 1) * STAGE;
        const uint32_t aH = sbase + 0 * TILEB + (uint32_t)wm * 64 * ROWB + laneOff;
        const uint32_t aL = aH + TILEB;
        const uint32_t bH = sbase + 2 * TILEB + (uint32_t)wn * 32 * ROWB + laneOff;
        const uint32_t bL = bH + TILEB;

        #pragma unroll
        for (int ks = 0; ks < 2; ks++) {
            const uint32_t ko = ks * 32;   // 16 halves * 2B
            uint32_t a[4][4], bh[2][4], bl[2][4];
            LDSM4(bh[0], bH + ko);
            LDSM4(bh[1], bH + 16 * ROWB + ko);
            LDSM4(bl[0], bL + ko);
            LDSM4(bl[1], bL + 16 * ROWB + ko);
            #pragma unroll
            for (int mt = 0; mt < 4; mt++) LDSM4(a[mt], aH + mt * 16 * ROWB + ko);

            #pragma unroll
            for (int mt = 0; mt < 4; mt++)
                #pragma unroll
                for (int nt = 0; nt < 4; nt++)
                    MMA(acc[mt][nt], a[mt], bh[nt >> 1][nt & 1], bh[nt >> 1][(nt & 1) + 2]);
            #pragma unroll
            for (int mt = 0; mt < 4; mt++)
                #pragma unroll
                for (int nt = 0; nt < 4; nt++)
                    MMA(acc[mt][nt], a[mt], bl[nt >> 1][nt & 1], bl[nt >> 1][(nt & 1) + 2]);

            #pragma unroll
            for (int mt = 0; mt < 4; mt++) LDSM4(a[mt], aL + mt * 16 * ROWB + ko);
            #pragma unroll
            for (int mt = 0; mt < 4; mt++)
                #pragma unroll
                for (int nt = 0; nt < 4; nt++)
                    MMA(acc[mt][nt], a[mt], bh[nt >> 1][nt & 1], bh[nt >> 1][(nt & 1) + 2]);
        }

        if (has_next) {
            char* st = dsm + ((c + 1) & 1) * STAGE;
            #pragma unroll
            for (int i = 0; i < 4; i++) {
                uint2 h, l;
                const uint32_t o = stoff + i * 32 * ROWB;
                split4(pa[i], h, l);
                *(uint2*)(st + 0 * TILEB + o) = h;
                *(uint2*)(st + 1 * TILEB + o) = l;
                split4(pb[i], h, l);
                *(uint2*)(st + 2 * TILEB + o) = h;
                *(uint2*)(st + 3 * TILEB + o) = l;
            }
            __syncthreads();
        }
    }

    // ---- epilogue
    const int lr = lane >> 2;          // 0..7
    const int lc = (lane & 3) * 2;     // 0,2,4,6
    #pragma unroll
    for (int mt = 0; mt < 4; mt++) {
        const int m0 = bm + wm * 64 + mt * 16 + lr;
        #pragma unroll
        for (int nt = 0; nt < 4; nt++) {
            const int n0 = bn + wn * 32 + nt * 8 + lc;
            float bx = 0.f, by = 0.f;
            if (bias) { bx = bias[n0]; by = bias[n0 + 1]; }
            float2 v0 = { acc[mt][nt][0] + bx, acc[mt][nt][1] + by };
            float2 v1 = { acc[mt][nt][2] + bx, acc[mt][nt][3] + by };
            *(float2*)(C + (size_t)m0 * N + n0)       = v0;
            *(float2*)(C + (size_t)(m0 + 8) * N + n0) = v1;
        }
    }
}

// ---------------------------------------------------------------------------
// V transpose: Vt[b][d][s] = V[b][s][d]   (makes AV gemm an NT gemm)
// ---------------------------------------------------------------------------
__global__ __launch_bounds__(256)
void transpose_v(const float* __restrict__ V, float* __restrict__ Vt)
{
    __shared__ float t[32][33];
    const int b  = blockIdx.z;
    const int d0 = blockIdx.x * 32;
    const int s0 = blockIdx.y * 32;
    const int tx = threadIdx.x;
    const int ty = threadIdx.y;
    const float* src = V  + (size_t)b * SEQ * DIM;
    float*       dst = Vt + (size_t)b * SEQ * DIM;
    #pragma unroll
    for (int j = 0; j < 32; j += 8)
        t[ty + j][tx] = src[(size_t)(s0 + ty + j) * DIM + d0 + tx];
    __syncthreads();
    #pragma unroll
    for (int j = 0; j < 32; j += 8)
        dst[(size_t)(d0 + ty + j) * SEQ + s0 + tx] = t[tx][ty + j];
}

// ---------------------------------------------------------------------------
// Row softmax over SEQ=2048 elements, fused with * NORM_FACT. In-place.
// ---------------------------------------------------------------------------
__global__ __launch_bounds__(256)
void softmax_rows(float* __restrict__ S)
{
    float* row = S + (size_t)blockIdx.x * SEQ;
    const int tid = threadIdx.x;

    float4 v0 = *(const float4*)(row + tid * 4);
    float4 v1 = *(const float4*)(row + 1024 + tid * 4);

    float m = fmaxf(fmaxf(fmaxf(v0.x, v0.y), fmaxf(v0.z, v0.w)),
                    fmaxf(fmaxf(v1.x, v1.y), fmaxf(v1.z, v1.w)));
    #pragma unroll
    for (int o = 16; o > 0; o >>= 1)
        m = fmaxf(m, __shfl_xor_sync(0xffffffffu, m, o));

    __shared__ float red[8];
    const int wid = tid >> 5, lane = tid & 31;
    if (lane == 0) red[wid] = m;
    __syncthreads();
    m = red[0];
    #pragma unroll
    for (int w = 1; w < 8; w++) m = fmaxf(m, red[w]);

    v0.x = __expf(v0.x - m); v0.y = __expf(v0.y - m);
    v0.z = __expf(v0.z - m); v0.w = __expf(v0.w - m);
    v1.x = __expf(v1.x - m); v1.y = __expf(v1.y - m);
    v1.z = __expf(v1.z - m); v1.w = __expf(v1.w - m);

    float s = (v0.x + v0.y) + (v0.z + v0.w) + (v1.x + v1.y) + (v1.z + v1.w);
    #pragma unroll
    for (int o = 16; o > 0; o >>= 1)
        s += __shfl_xor_sync(0xffffffffu, s, o);

    __syncthreads();
    __shared__ float red2[8];
    if (lane == 0) red2[wid] = s;
    __syncthreads();
    s = red2[0];
    #pragma unroll
    for (int w = 1; w < 8; w++) s += red2[w];

    const float scale = NORM_FACT / s;
    v0.x *= scale; v0.y *= scale; v0.z *= scale; v0.w *= scale;
    v1.x *= scale; v1.y *= scale; v1.z *= scale; v1.w *= scale;

    *(float4*)(row + tid * 4)        = v0;
    *(float4*)(row + 1024 + tid * 4) = v1;
}

// ---------------------------------------------------------------------------
extern "C" void kernel_launch(void* const* d_in, const int* in_sizes, int n_in,
                              void* d_out, int out_size)
{
    const float* x  = (const float*)d_in[0];
    const float* Wq = (const float*)d_in[1];
    const float* bq = (const float*)d_in[2];
    const float* Wk = (const float*)d_in[3];
    const float* bk = (const float*)d_in[4];
    const float* Wv = (const float*)d_in[5];
    const float* bv = (const float*)d_in[6];
    float* out = (float*)d_out;

    float *Q, *K, *V, *Vt, *P;
    cudaGetSymbolAddress((void**)&Q,  g_Q);
    cudaGetSymbolAddress((void**)&K,  g_K);
    cudaGetSymbolAddress((void**)&V,  g_V);
    cudaGetSymbolAddress((void**)&Vt, g_Vt);
    cudaGetSymbolAddress((void**)&P,  g_P);

    cudaFuncSetAttribute(gemm_mma, cudaFuncAttributeMaxDynamicSharedMemorySize, SMEM_TOTAL);

    // QKV projections: [8192,1024] = x @ W^T + b
    {
        dim3 grid(DIM / 128, (BATCH * SEQ) / 128, 1);
        gemm_mma<<<grid, 256, SMEM_TOTAL>>>(x, Wq, bq, Q, BATCH * SEQ, DIM, DIM, 0, 0, 0);
        gemm_mma<<<grid, 256, SMEM_TOTAL>>>(x, Wk, bk, K, BATCH * SEQ, DIM, DIM, 0, 0, 0);
        gemm_mma<<<grid, 256, SMEM_TOTAL>>>(x, Wv, bv, V, BATCH * SEQ, DIM, DIM, 0, 0, 0);
    }

    // Vt = V^T per batch
    {
        dim3 grid(DIM / 32, SEQ / 32, BATCH);
        transpose_v<<<grid, dim3(32, 8)>>>(V, Vt);
    }

    // scores[b] = Q[b] @ K[b]^T
    {
        dim3 grid(SEQ / 128, SEQ / 128, BATCH);
        gemm_mma<<<grid, 256, SMEM_TOTAL>>>(Q, K, nullptr, P, SEQ, SEQ, DIM,
                                            (size_t)SEQ * DIM, (size_t)SEQ * DIM,
                                            (size_t)SEQ * SEQ);
    }

    // softmax rows (with 1/sqrt(Dk) folded in)
    softmax_rows<<<BATCH * SEQ, 256>>>(P);

    // out[b] = P[b] @ Vt[b]^T
    {
        dim3 grid(DIM / 128, SEQ / 128, BATCH);
        gemm_mma<<<grid, 256, SMEM_TOTAL>>>(P, Vt, nullptr, out, SEQ, DIM, SEQ,
                                            (size_t)SEQ * SEQ, (size_t)SEQ * DIM,
                                            (size_t)SEQ * DIM);
    }
}

// round 5
// speedup vs baseline: 2.2659x; 1.8074x over previous
#include <cuda_runtime.h>
#include <cuda_bf16.h>
#include <cstdint>

#define BATCH 4
#define SEQ   2048
#define DIM   1024
#define NORM_FACT 0.03125f   // 1/sqrt(1024), applied POST-softmax per reference

typedef __nv_bfloat16 bf16;

// ---------------------------------------------------------------------------
// Scratch (allocation-free rule: __device__ globals). All GEMM operands are
// stored PRE-SPLIT as bf16 hi/lo pairs.
// ---------------------------------------------------------------------------
#define NX  ((size_t)BATCH * SEQ * DIM)   // 8M
#define NW  ((size_t)DIM * DIM)           // 1M
#define NP  ((size_t)BATCH * SEQ * SEQ)   // 16M

__device__ __align__(256) bf16 g_xh[NX],  g_xl[NX];
__device__ __align__(256) bf16 g_Wqh[NW], g_Wql[NW];
__device__ __align__(256) bf16 g_Wkh[NW], g_Wkl[NW];
__device__ __align__(256) bf16 g_Wvh[NW], g_Wvl[NW];
__device__ __align__(256) bf16 g_Qh[NX],  g_Ql[NX];
__device__ __align__(256) bf16 g_Kh[NX],  g_Kl[NX];
__device__ __align__(256) bf16 g_Vh[NX],  g_Vl[NX];
__device__ __align__(256) bf16 g_Vth[NX], g_Vtl[NX];
__device__ __align__(256) bf16 g_Ph[NP],  g_Pl[NP];
__device__ __align__(256) float g_P[NP];

// ---------------------------------------------------------------------------
// Smem: 2 stages x { Ah, Al, Bh, Bl } tiles of 128 rows x 32 bf16,
// row stride 80 B -> ldmatrix conflict-free, cp.async 16B-aligned.
// ---------------------------------------------------------------------------
#define ROWB   80
#define TILEB  (128 * ROWB)          // 10240
#define STAGE  (4 * TILEB)           // 40960
#define SMEM_TOTAL (2 * STAGE)       // 81920

extern __shared__ char dsm[];

__device__ __forceinline__ uint32_t smem_u32(const void* p) {
    uint32_t a;
    asm("{ .reg .u64 t; cvta.to.shared.u64 t, %1; cvt.u32.u64 %0, t; }"
        : "=r"(a) : "l"(p));
    return a;
}

#define CPA16(dst, src) \
    asm volatile("cp.async.cg.shared.global [%0], [%1], 16;" :: "r"(dst), "l"(src))
#define CPA_COMMIT() asm volatile("cp.async.commit_group;" ::: "memory")
#define CPA_WAIT0()  asm volatile("cp.async.wait_group 0;" ::: "memory")

#define LDSM4(R, addr)                                                        \
    asm volatile("ldmatrix.sync.aligned.m8n8.x4.shared.b16 {%0,%1,%2,%3}, [%4];" \
                 : "=r"((R)[0]), "=r"((R)[1]), "=r"((R)[2]), "=r"((R)[3])     \
                 : "r"(addr))

#define MMA(cc, A, b0, b1)                                                    \
    asm volatile("mma.sync.aligned.m16n8k16.row.col.f32.bf16.bf16.f32 "       \
                 "{%0,%1,%2,%3},{%4,%5,%6,%7},{%8,%9},{%0,%1,%2,%3};"         \
                 : "+f"((cc)[0]), "+f"((cc)[1]), "+f"((cc)[2]), "+f"((cc)[3]) \
                 : "r"((A)[0]), "r"((A)[1]), "r"((A)[2]), "r"((A)[3]),        \
                   "r"(b0), "r"(b1))

__device__ __forceinline__ uint32_t pk(bf16 a, bf16 b) {
    return (uint32_t)__bfloat16_as_ushort(a) | ((uint32_t)__bfloat16_as_ushort(b) << 16);
}

__device__ __forceinline__ void split1(float v, bf16& h, bf16& l) {
    h = __float2bfloat16_rn(v);
    l = __float2bfloat16_rn(v - __bfloat162float(h));
}

// ---------------------------------------------------------------------------
// fp32 -> (hi, lo) bf16 split conversion, grid-stride over float4s.
// ---------------------------------------------------------------------------
__global__ __launch_bounds__(256)
void split_f32(const float* __restrict__ in, bf16* __restrict__ hi,
               bf16* __restrict__ lo, size_t n4)
{
    for (size_t i = (size_t)blockIdx.x * blockDim.x + threadIdx.x; i < n4;
         i += (size_t)gridDim.x * blockDim.x) {
        float4 v = ((const float4*)in)[i];
        bf16 h0, h1, h2, h3, l0, l1, l2, l3;
        split1(v.x, h0, l0); split1(v.y, h1, l1);
        split1(v.z, h2, l2); split1(v.w, h3, l3);
        ((uint2*)hi)[i] = make_uint2(pk(h0, h1), pk(h2, h3));
        ((uint2*)lo)[i] = make_uint2(pk(l0, l1), pk(l2, l3));
    }
}

// ---------------------------------------------------------------------------
// Split-precision NT GEMM on HMMA, operands pre-split bf16 in global:
//   C[M,N] = (Ah+Al)[M,K] * (Bh+Bl)[N,K]^T (+ bias), 3-term (hh + hl + lh).
// CTA 128x128, k-chunk 32, cp.async double-buffer, 8 warps, warp 64x32.
// Output: fp32 (Cf) or split bf16 (Ch, Cl) — whichever is non-null.
// ---------------------------------------------------------------------------
__global__ __launch_bounds__(256, 2)
void gemm_sp(const bf16* __restrict__ Ah, const bf16* __restrict__ Al,
             const bf16* __restrict__ Bh, const bf16* __restrict__ Bl,
             const float* __restrict__ bias,
             float* __restrict__ Cf, bf16* __restrict__ Ch, bf16* __restrict__ Cl,
             int M, int N, int K, size_t sA, size_t sB, size_t sC)
{
    const size_t zA = (size_t)blockIdx.z * sA;
    const size_t zB = (size_t)blockIdx.z * sB;
    const size_t zC = (size_t)blockIdx.z * sC;

    const int tid  = threadIdx.x;
    const int wid  = tid >> 5;
    const int lane = tid & 31;
    const int wm   = wid >> 2;
    const int wn   = wid & 3;
    const int bm = blockIdx.y * 128;
    const int bn = blockIdx.x * 128;

    // cp.async loader: thread -> row (tid>>1), 32-byte segment (tid&1)
    const int lrow  = tid >> 1;
    const int lsegB = (tid & 1) * 32;            // byte offset in 64B row
    const uint32_t so = (uint32_t)lrow * ROWB + (uint32_t)lsegB;
    const bf16* pAh = Ah + zA + (size_t)(bm + lrow) * K + lsegB / 2;
    const bf16* pAl = Al + zA + (size_t)(bm + lrow) * K + lsegB / 2;
    const bf16* pBh = Bh + zB + (size_t)(bn + lrow) * K + lsegB / 2;
    const bf16* pBl = Bl + zB + (size_t)(bn + lrow) * K + lsegB / 2;

    const uint32_t sb = smem_u32(dsm);
    const uint32_t laneOff = (uint32_t)(lane & 15) * ROWB + (uint32_t)(lane >> 4) * 16;

    float acc[4][4][4] = {};

    // prologue: stage 0
    {
        const uint32_t s0 = sb;
        CPA16(s0 + 0 * TILEB + so,      pAh);
        CPA16(s0 + 0 * TILEB + so + 16, pAh + 8);
        CPA16(s0 + 1 * TILEB + so,      pAl);
        CPA16(s0 + 1 * TILEB + so + 16, pAl + 8);
        CPA16(s0 + 2 * TILEB + so,      pBh);
        CPA16(s0 + 2 * TILEB + so + 16, pBh + 8);
        CPA16(s0 + 3 * TILEB + so,      pBl);
        CPA16(s0 + 3 * TILEB + so + 16, pBl + 8);
        CPA_COMMIT();
    }

    const int NC = K >> 5;
    for (int c = 0; c < NC; c++) {
        CPA_WAIT0();
        __syncthreads();

        if (c + 1 < NC) {
            const int k1 = (c + 1) << 5;
            const uint32_t s1 = sb + (uint32_t)((c + 1) & 1) * STAGE;
            CPA16(s1 + 0 * TILEB + so,      pAh + k1);
            CPA16(s1 + 0 * TILEB + so + 16, pAh + k1 + 8);
            CPA16(s1 + 1 * TILEB + so,      pAl + k1);
            CPA16(s1 + 1 * TILEB + so + 16, pAl + k1 + 8);
            CPA16(s1 + 2 * TILEB + so,      pBh + k1);
            CPA16(s1 + 2 * TILEB + so + 16, pBh + k1 + 8);
            CPA16(s1 + 3 * TILEB + so,      pBl + k1);
            CPA16(s1 + 3 * TILEB + so + 16, pBl + k1 + 8);
            CPA_COMMIT();
        }

        const uint32_t sbase = sb + (uint32_t)(c & 1) * STAGE;
        const uint32_t aH = sbase + 0 * TILEB + (uint32_t)wm * 64 * ROWB + laneOff;
        const uint32_t aL = aH + TILEB;
        const uint32_t bH = sbase + 2 * TILEB + (uint32_t)wn * 32 * ROWB + laneOff;
        const uint32_t bL = bH + TILEB;

        #pragma unroll
        for (int ks = 0; ks < 2; ks++) {
            const uint32_t ko = ks * 32;
            uint32_t a[4][4], bh[2][4], bl[2][4];
            LDSM4(bh[0], bH + ko);
            LDSM4(bh[1], bH + 16 * ROWB + ko);
            LDSM4(bl[0], bL + ko);
            LDSM4(bl[1], bL + 16 * ROWB + ko);
            #pragma unroll
            for (int mt = 0; mt < 4; mt++) LDSM4(a[mt], aH + mt * 16 * ROWB + ko);

            #pragma unroll
            for (int mt = 0; mt < 4; mt++)
                #pragma unroll
                for (int nt = 0; nt < 4; nt++)
                    MMA(acc[mt][nt], a[mt], bh[nt >> 1][nt & 1], bh[nt >> 1][(nt & 1) + 2]);
            #pragma unroll
            for (int mt = 0; mt < 4; mt++)
                #pragma unroll
                for (int nt = 0; nt < 4; nt++)
                    MMA(acc[mt][nt], a[mt], bl[nt >> 1][nt & 1], bl[nt >> 1][(nt & 1) + 2]);

            #pragma unroll
            for (int mt = 0; mt < 4; mt++) LDSM4(a[mt], aL + mt * 16 * ROWB + ko);
            #pragma unroll
            for (int mt = 0; mt < 4; mt++)
                #pragma unroll
                for (int nt = 0; nt < 4; nt++)
                    MMA(acc[mt][nt], a[mt], bh[nt >> 1][nt & 1], bh[nt >> 1][(nt & 1) + 2]);
        }
    }

    // ---- epilogue
    const int lr = lane >> 2;
    const int lc = (lane & 3) * 2;
    #pragma unroll
    for (int mt = 0; mt < 4; mt++) {
        const int m0 = bm + wm * 64 + mt * 16 + lr;
        #pragma unroll
        for (int nt = 0; nt < 4; nt++) {
            const int n0 = bn + wn * 32 + nt * 8 + lc;
            float bx = 0.f, by = 0.f;
            if (bias) { bx = bias[n0]; by = bias[n0 + 1]; }
            float v00 = acc[mt][nt][0] + bx, v01 = acc[mt][nt][1] + by;
            float v10 = acc[mt][nt][2] + bx, v11 = acc[mt][nt][3] + by;
            if (Cf) {
                *(float2*)(Cf + zC + (size_t)m0 * N + n0)       = make_float2(v00, v01);
                *(float2*)(Cf + zC + (size_t)(m0 + 8) * N + n0) = make_float2(v10, v11);
            } else {
                bf16 h0, h1, l0, l1;
                split1(v00, h0, l0); split1(v01, h1, l1);
                *(uint32_t*)(Ch + zC + (size_t)m0 * N + n0) = pk(h0, h1);
                *(uint32_t*)(Cl + zC + (size_t)m0 * N + n0) = pk(l0, l1);
                split1(v10, h0, l0); split1(v11, h1, l1);
                *(uint32_t*)(Ch + zC + (size_t)(m0 + 8) * N + n0) = pk(h0, h1);
                *(uint32_t*)(Cl + zC + (size_t)(m0 + 8) * N + n0) = pk(l0, l1);
            }
        }
    }
}

// ---------------------------------------------------------------------------
// bf16 transpose: Vt[b][d][s] = V[b][s][d]
// ---------------------------------------------------------------------------
__global__ __launch_bounds__(256)
void transpose_bf16(const bf16* __restrict__ V, bf16* __restrict__ Vt)
{
    __shared__ bf16 t[32][33];
    const int b  = blockIdx.z;
    const int d0 = blockIdx.x * 32;
    const int s0 = blockIdx.y * 32;
    const int tx = threadIdx.x;
    const int ty = threadIdx.y;
    const bf16* src = V  + (size_t)b * SEQ * DIM;
    bf16*       dst = Vt + (size_t)b * SEQ * DIM;
    #pragma unroll
    for (int j = 0; j < 32; j += 8)
        t[ty + j][tx] = src[(size_t)(s0 + ty + j) * DIM + d0 + tx];
    __syncthreads();
    #pragma unroll
    for (int j = 0; j < 32; j += 8)
        dst[(size_t)(d0 + ty + j) * SEQ + s0 + tx] = t[tx][ty + j];
}

// ---------------------------------------------------------------------------
// Row softmax over SEQ=2048, * NORM_FACT, output split bf16 (Ph, Pl).
// ---------------------------------------------------------------------------
__global__ __launch_bounds__(256)
void softmax_split(const float* __restrict__ S, bf16* __restrict__ Ph,
                   bf16* __restrict__ Pl)
{
    const float* row = S + (size_t)blockIdx.x * SEQ;
    const int tid = threadIdx.x;

    float4 v0 = *(const float4*)(row + tid * 4);
    float4 v1 = *(const float4*)(row + 1024 + tid * 4);

    float m = fmaxf(fmaxf(fmaxf(v0.x, v0.y), fmaxf(v0.z, v0.w)),
                    fmaxf(fmaxf(v1.x, v1.y), fmaxf(v1.z, v1.w)));
    #pragma unroll
    for (int o = 16; o > 0; o >>= 1)
        m = fmaxf(m, __shfl_xor_sync(0xffffffffu, m, o));

    __shared__ float red[8];
    const int wid = tid >> 5, lane = tid & 31;
    if (lane == 0) red[wid] = m;
    __syncthreads();
    m = red[0];
    #pragma unroll
    for (int w = 1; w < 8; w++) m = fmaxf(m, red[w]);

    v0.x = __expf(v0.x - m); v0.y = __expf(v0.y - m);
    v0.z = __expf(v0.z - m); v0.w = __expf(v0.w - m);
    v1.x = __expf(v1.x - m); v1.y = __expf(v1.y - m);
    v1.z = __expf(v1.z - m); v1.w = __expf(v1.w - m);

    float s = (v0.x + v0.y) + (v0.z + v0.w) + (v1.x + v1.y) + (v1.z + v1.w);
    #pragma unroll
    for (int o = 16; o > 0; o >>= 1)
        s += __shfl_xor_sync(0xffffffffu, s, o);

    __shared__ float red2[8];
    if (lane == 0) red2[wid] = s;
    __syncthreads();
    s = red2[0];
    #pragma unroll
    for (int w = 1; w < 8; w++) s += red2[w];

    const float scale = NORM_FACT / s;
    v0.x *= scale; v0.y *= scale; v0.z *= scale; v0.w *= scale;
    v1.x *= scale; v1.y *= scale; v1.z *= scale; v1.w *= scale;

    bf16* ph = Ph + (size_t)blockIdx.x * SEQ;
    bf16* pl = Pl + (size_t)blockIdx.x * SEQ;
    bf16 h0, h1, h2, h3, l0, l1, l2, l3;
    split1(v0.x, h0, l0); split1(v0.y, h1, l1);
    split1(v0.z, h2, l2); split1(v0.w, h3, l3);
    *(uint2*)(ph + tid * 4) = make_uint2(pk(h0, h1), pk(h2, h3));
    *(uint2*)(pl + tid * 4) = make_uint2(pk(l0, l1), pk(l2, l3));
    split1(v1.x, h0, l0); split1(v1.y, h1, l1);
    split1(v1.z, h2, l2); split1(v1.w, h3, l3);
    *(uint2*)(ph + 1024 + tid * 4) = make_uint2(pk(h0, h1), pk(h2, h3));
    *(uint2*)(pl + 1024 + tid * 4) = make_uint2(pk(l0, l1), pk(l2, l3));
}

// ---------------------------------------------------------------------------
extern "C" void kernel_launch(void* const* d_in, const int* in_sizes, int n_in,
                              void* d_out, int out_size)
{
    const float* x  = (const float*)d_in[0];
    const float* Wq = (const float*)d_in[1];
    const float* bq = (const float*)d_in[2];
    const float* Wk = (const float*)d_in[3];
    const float* bk = (const float*)d_in[4];
    const float* Wv = (const float*)d_in[5];
    const float* bv = (const float*)d_in[6];
    float* out = (float*)d_out;

    bf16 *xh, *xl, *Wqh, *Wql, *Wkh, *Wkl, *Wvh, *Wvl;
    bf16 *Qh, *Ql, *Kh, *Kl, *Vh, *Vl, *Vth, *Vtl, *Ph, *Pl;
    float* P;
    cudaGetSymbolAddress((void**)&xh,  g_xh);  cudaGetSymbolAddress((void**)&xl,  g_xl);
    cudaGetSymbolAddress((void**)&Wqh, g_Wqh); cudaGetSymbolAddress((void**)&Wql, g_Wql);
    cudaGetSymbolAddress((void**)&Wkh, g_Wkh); cudaGetSymbolAddress((void**)&Wkl, g_Wkl);
    cudaGetSymbolAddress((void**)&Wvh, g_Wvh); cudaGetSymbolAddress((void**)&Wvl, g_Wvl);
    cudaGetSymbolAddress((void**)&Qh,  g_Qh);  cudaGetSymbolAddress((void**)&Ql,  g_Ql);
    cudaGetSymbolAddress((void**)&Kh,  g_Kh);  cudaGetSymbolAddress((void**)&Kl,  g_Kl);
    cudaGetSymbolAddress((void**)&Vh,  g_Vh);  cudaGetSymbolAddress((void**)&Vl,  g_Vl);
    cudaGetSymbolAddress((void**)&Vth, g_Vth); cudaGetSymbolAddress((void**)&Vtl, g_Vtl);
    cudaGetSymbolAddress((void**)&Ph,  g_Ph);  cudaGetSymbolAddress((void**)&Pl,  g_Pl);
    cudaGetSymbolAddress((void**)&P,   g_P);

    cudaFuncSetAttribute(gemm_sp, cudaFuncAttributeMaxDynamicSharedMemorySize, SMEM_TOTAL);

    // 0) split inputs
    split_f32<<<1024, 256>>>(x,  xh,  xl,  NX / 4);
    split_f32<<<512,  256>>>(Wq, Wqh, Wql, NW / 4);
    split_f32<<<512,  256>>>(Wk, Wkh, Wkl, NW / 4);
    split_f32<<<512,  256>>>(Wv, Wvh, Wvl, NW / 4);

    // 1) QKV projections -> split outputs
    {
        dim3 grid(DIM / 128, (BATCH * SEQ) / 128, 1);
        gemm_sp<<<grid, 256, SMEM_TOTAL>>>(xh, xl, Wqh, Wql, bq, nullptr, Qh, Ql,
                                           BATCH * SEQ, DIM, DIM, 0, 0, 0);
        gemm_sp<<<grid, 256, SMEM_TOTAL>>>(xh, xl, Wkh, Wkl, bk, nullptr, Kh, Kl,
                                           BATCH * SEQ, DIM, DIM, 0, 0, 0);
        gemm_sp<<<grid, 256, SMEM_TOTAL>>>(xh, xl, Wvh, Wvl, bv, nullptr, Vh, Vl,
                                           BATCH * SEQ, DIM, DIM, 0, 0, 0);
    }

    // 2) Vt = V^T (hi and lo separately)
    {
        dim3 grid(DIM / 32, SEQ / 32, BATCH);
        transpose_bf16<<<grid, dim3(32, 8)>>>(Vh, Vth);
        transpose_bf16<<<grid, dim3(32, 8)>>>(Vl, Vtl);
    }

    // 3) scores[b] = Q[b] @ K[b]^T  -> fp32 P
    {
        dim3 grid(SEQ / 128, SEQ / 128, BATCH);
        gemm_sp<<<grid, 256, SMEM_TOTAL>>>(Qh, Ql, Kh, Kl, nullptr, P, nullptr, nullptr,
                                           SEQ, SEQ, DIM,
                                           (size_t)SEQ * DIM, (size_t)SEQ * DIM,
                                           (size_t)SEQ * SEQ);
    }

    // 4) softmax rows -> split (Ph, Pl), NORM folded
    softmax_split<<<BATCH * SEQ, 256>>>(P, Ph, Pl);

    // 5) out[b] = P[b] @ Vt[b]^T
    {
        dim3 grid(DIM / 128, SEQ / 128, BATCH);
        gemm_sp<<<grid, 256, SMEM_TOTAL>>>(Ph, Pl, Vth, Vtl, nullptr, out, nullptr, nullptr,
                                           SEQ, DIM, SEQ,
                                           (size_t)SEQ * SEQ, (size_t)SEQ * DIM,
                                           (size_t)SEQ * DIM);
    }
}